// round 1
// baseline (speedup 1.0000x reference)
#include <cuda_runtime.h>
#include <math.h>

#define NB 8
#define NC 256
#define NL 2048          // L == M == IN_DIM
#define NR (NB * NC)     // 2048 rows for the QKV GEMMs

// Scratch (module-level device arrays: allocation-free kernel_launch)
__device__ float g_Q[NR * NL];                 // 16 MB, layout [B][C][M]
__device__ float g_K[NR * NL];                 // 16 MB
__device__ float g_V[NR * NL];                 // 16 MB
__device__ float g_S[33554432];                // 128 MB, [B][L][M] scores/probs

// ---------------------------------------------------------------------------
// Kernel 1: QKV projections.  Y[r, m] = sum_l X[r, l] * W[m, l] + b[m]
// Both operands K(l)-major. blockIdx.z selects {Q, K, V}.
// ---------------------------------------------------------------------------
__global__ __launch_bounds__(256, 2)
void qkv_kernel(const float* __restrict__ x,
                const float* __restrict__ Wq, const float* __restrict__ bq,
                const float* __restrict__ Wk, const float* __restrict__ bk,
                const float* __restrict__ Wv, const float* __restrict__ bv)
{
    __shared__ float As[8][132];
    __shared__ float Bs[8][132];

    const float* W;
    const float* bias;
    float* out;
    if (blockIdx.z == 0)      { W = Wq; bias = bq; out = g_Q; }
    else if (blockIdx.z == 1) { W = Wk; bias = bk; out = g_K; }
    else                      { W = Wv; bias = bv; out = g_V; }

    const int row0 = blockIdx.y * 128;
    const int col0 = blockIdx.x * 128;
    const int tid = threadIdx.x;
    const int tx = tid & 15, ty = tid >> 4;

    const int lr = tid >> 1;         // 0..127
    const int lk = (tid & 1) * 4;    // 0 or 4

    float acc[8][8];
#pragma unroll
    for (int i = 0; i < 8; i++)
#pragma unroll
        for (int j = 0; j < 8; j++) acc[i][j] = 0.0f;

    const float* Aptr = x + (size_t)(row0 + lr) * NL + lk;
    const float* Bptr = W + (size_t)(col0 + lr) * NL + lk;

    for (int k0 = 0; k0 < NL; k0 += 8) {
        float4 a = *(const float4*)(Aptr + k0);
        float4 b = *(const float4*)(Bptr + k0);
        As[lk + 0][lr] = a.x; As[lk + 1][lr] = a.y;
        As[lk + 2][lr] = a.z; As[lk + 3][lr] = a.w;
        Bs[lk + 0][lr] = b.x; Bs[lk + 1][lr] = b.y;
        Bs[lk + 2][lr] = b.z; Bs[lk + 3][lr] = b.w;
        __syncthreads();
#pragma unroll
        for (int k = 0; k < 8; k++) {
            float4 a0 = *(const float4*)&As[k][ty * 8];
            float4 a1 = *(const float4*)&As[k][ty * 8 + 4];
            float4 b0 = *(const float4*)&Bs[k][tx * 8];
            float4 b1 = *(const float4*)&Bs[k][tx * 8 + 4];
            float av[8] = {a0.x, a0.y, a0.z, a0.w, a1.x, a1.y, a1.z, a1.w};
            float bw[8] = {b0.x, b0.y, b0.z, b0.w, b1.x, b1.y, b1.z, b1.w};
#pragma unroll
            for (int i = 0; i < 8; i++)
#pragma unroll
                for (int j = 0; j < 8; j++)
                    acc[i][j] = fmaf(av[i], bw[j], acc[i][j]);
        }
        __syncthreads();
    }

    float bb[8];
#pragma unroll
    for (int j = 0; j < 8; j++) bb[j] = bias[col0 + tx * 8 + j];

#pragma unroll
    for (int i = 0; i < 8; i++) {
        const int r = row0 + ty * 8 + i;
        float4 v0, v1;
        v0.x = acc[i][0] + bb[0]; v0.y = acc[i][1] + bb[1];
        v0.z = acc[i][2] + bb[2]; v0.w = acc[i][3] + bb[3];
        v1.x = acc[i][4] + bb[4]; v1.y = acc[i][5] + bb[5];
        v1.z = acc[i][6] + bb[6]; v1.w = acc[i][7] + bb[7];
        *(float4*)&out[(size_t)r * NL + col0 + tx * 8]     = v0;
        *(float4*)&out[(size_t)r * NL + col0 + tx * 8 + 4] = v1;
    }
}

// ---------------------------------------------------------------------------
// Kernel 2: scores. S[b][l][m] = scale * sum_c Q[b][c][l] * K[b][c][m]
// Contraction over c (outer dim of Q/K): tiles are already k-plane contiguous,
// no smem transpose needed.
// ---------------------------------------------------------------------------
__global__ __launch_bounds__(256, 2)
void score_kernel()
{
    __shared__ float As[8][132];
    __shared__ float Bs[8][132];

    const int b = blockIdx.z;
    const float* Qb = g_Q + (size_t)b * NC * NL;
    const float* Kb = g_K + (size_t)b * NC * NL;
    float* Sb = g_S + (size_t)b * NL * NL;

    const int l0 = blockIdx.y * 128;
    const int m0 = blockIdx.x * 128;
    const int tid = threadIdx.x;
    const int tx = tid & 15, ty = tid >> 4;

    const int lc = tid >> 5;         // 0..7  (c within tile)
    const int ll = (tid & 31) * 4;   // 0..124

    float acc[8][8];
#pragma unroll
    for (int i = 0; i < 8; i++)
#pragma unroll
        for (int j = 0; j < 8; j++) acc[i][j] = 0.0f;

    const float* Ap = Qb + (size_t)lc * NL + l0 + ll;
    const float* Bp = Kb + (size_t)lc * NL + m0 + ll;

    for (int c0 = 0; c0 < NC; c0 += 8) {
        float4 a = *(const float4*)(Ap + (size_t)c0 * NL);
        float4 b4 = *(const float4*)(Bp + (size_t)c0 * NL);
        *(float4*)&As[lc][ll] = a;
        *(float4*)&Bs[lc][ll] = b4;
        __syncthreads();
#pragma unroll
        for (int k = 0; k < 8; k++) {
            float4 a0 = *(const float4*)&As[k][ty * 8];
            float4 a1 = *(const float4*)&As[k][ty * 8 + 4];
            float4 b0 = *(const float4*)&Bs[k][tx * 8];
            float4 b1 = *(const float4*)&Bs[k][tx * 8 + 4];
            float av[8] = {a0.x, a0.y, a0.z, a0.w, a1.x, a1.y, a1.z, a1.w};
            float bw[8] = {b0.x, b0.y, b0.z, b0.w, b1.x, b1.y, b1.z, b1.w};
#pragma unroll
            for (int i = 0; i < 8; i++)
#pragma unroll
                for (int j = 0; j < 8; j++)
                    acc[i][j] = fmaf(av[i], bw[j], acc[i][j]);
        }
        __syncthreads();
    }

    const float scale = 0.022097086912079612f;  // 1/sqrt(2048)
#pragma unroll
    for (int i = 0; i < 8; i++) {
        const int l = l0 + ty * 8 + i;
        float4 v0, v1;
        v0.x = acc[i][0] * scale; v0.y = acc[i][1] * scale;
        v0.z = acc[i][2] * scale; v0.w = acc[i][3] * scale;
        v1.x = acc[i][4] * scale; v1.y = acc[i][5] * scale;
        v1.z = acc[i][6] * scale; v1.w = acc[i][7] * scale;
        *(float4*)&Sb[(size_t)l * NL + m0 + tx * 8]     = v0;
        *(float4*)&Sb[(size_t)l * NL + m0 + tx * 8 + 4] = v1;
    }
}

// ---------------------------------------------------------------------------
// Kernel 3: row softmax over m (in place on g_S). One block per (b, l) row.
// ---------------------------------------------------------------------------
__global__ void softmax_kernel()
{
    const int row = blockIdx.x;  // 0 .. NB*NL-1
    float* p = g_S + (size_t)row * NL;
    const int tid = threadIdx.x;

    float v[8];
    float m = -1e30f;
#pragma unroll
    for (int j = 0; j < 8; j++) {
        v[j] = p[tid + j * 256];
        m = fmaxf(m, v[j]);
    }

    __shared__ float red[256];
    red[tid] = m;
    __syncthreads();
    for (int s = 128; s > 0; s >>= 1) {
        if (tid < s) red[tid] = fmaxf(red[tid], red[tid + s]);
        __syncthreads();
    }
    m = red[0];
    __syncthreads();

    float sum = 0.0f;
#pragma unroll
    for (int j = 0; j < 8; j++) {
        v[j] = __expf(v[j] - m);
        sum += v[j];
    }
    red[tid] = sum;
    __syncthreads();
    for (int s = 128; s > 0; s >>= 1) {
        if (tid < s) red[tid] += red[tid + s];
        __syncthreads();
    }
    const float inv = 1.0f / red[0];

#pragma unroll
    for (int j = 0; j < 8; j++)
        p[tid + j * 256] = v[j] * inv;
}

// ---------------------------------------------------------------------------
// Kernel 4: output. O[b][c][l] = sum_m V[b][c][m] * P[b][l][m]
// Both operands K(m)-major.
// ---------------------------------------------------------------------------
__global__ __launch_bounds__(256, 2)
void out_kernel(float* __restrict__ out)
{
    __shared__ float As[8][132];
    __shared__ float Bs[8][132];

    const int b = blockIdx.z;
    const float* Vb = g_V + (size_t)b * NC * NL;
    const float* Pb = g_S + (size_t)b * NL * NL;
    float* Ob = out + (size_t)b * NC * NL;

    const int c0 = blockIdx.y * 128;
    const int l0 = blockIdx.x * 128;
    const int tid = threadIdx.x;
    const int tx = tid & 15, ty = tid >> 4;

    const int lr = tid >> 1;
    const int lk = (tid & 1) * 4;

    float acc[8][8];
#pragma unroll
    for (int i = 0; i < 8; i++)
#pragma unroll
        for (int j = 0; j < 8; j++) acc[i][j] = 0.0f;

    const float* Aptr = Vb + (size_t)(c0 + lr) * NL + lk;
    const float* Bptr = Pb + (size_t)(l0 + lr) * NL + lk;

    for (int k0 = 0; k0 < NL; k0 += 8) {
        float4 a = *(const float4*)(Aptr + k0);
        float4 b4 = *(const float4*)(Bptr + k0);
        As[lk + 0][lr] = a.x;  As[lk + 1][lr] = a.y;
        As[lk + 2][lr] = a.z;  As[lk + 3][lr] = a.w;
        Bs[lk + 0][lr] = b4.x; Bs[lk + 1][lr] = b4.y;
        Bs[lk + 2][lr] = b4.z; Bs[lk + 3][lr] = b4.w;
        __syncthreads();
#pragma unroll
        for (int k = 0; k < 8; k++) {
            float4 a0 = *(const float4*)&As[k][ty * 8];
            float4 a1 = *(const float4*)&As[k][ty * 8 + 4];
            float4 b0 = *(const float4*)&Bs[k][tx * 8];
            float4 b1 = *(const float4*)&Bs[k][tx * 8 + 4];
            float av[8] = {a0.x, a0.y, a0.z, a0.w, a1.x, a1.y, a1.z, a1.w};
            float bw[8] = {b0.x, b0.y, b0.z, b0.w, b1.x, b1.y, b1.z, b1.w};
#pragma unroll
            for (int i = 0; i < 8; i++)
#pragma unroll
                for (int j = 0; j < 8; j++)
                    acc[i][j] = fmaf(av[i], bw[j], acc[i][j]);
        }
        __syncthreads();
    }

#pragma unroll
    for (int i = 0; i < 8; i++) {
        const int c = c0 + ty * 8 + i;
        float4 v0, v1;
        v0.x = acc[i][0]; v0.y = acc[i][1]; v0.z = acc[i][2]; v0.w = acc[i][3];
        v1.x = acc[i][4]; v1.y = acc[i][5]; v1.z = acc[i][6]; v1.w = acc[i][7];
        *(float4*)&Ob[(size_t)c * NL + l0 + tx * 8]     = v0;
        *(float4*)&Ob[(size_t)c * NL + l0 + tx * 8 + 4] = v1;
    }
}

// ---------------------------------------------------------------------------
extern "C" void kernel_launch(void* const* d_in, const int* in_sizes, int n_in,
                              void* d_out, int out_size)
{
    const float* x  = (const float*)d_in[0];
    const float* Wq = (const float*)d_in[1];
    const float* bq = (const float*)d_in[2];
    const float* Wk = (const float*)d_in[3];
    const float* bk = (const float*)d_in[4];
    const float* Wv = (const float*)d_in[5];
    const float* bv = (const float*)d_in[6];
    float* out = (float*)d_out;

    qkv_kernel<<<dim3(NL / 128, NR / 128, 3), 256>>>(x, Wq, bq, Wk, bk, Wv, bv);
    score_kernel<<<dim3(NL / 128, NL / 128, NB), 256>>>();
    softmax_kernel<<<NB * NL, 256>>>();
    out_kernel<<<dim3(NL / 128, NC / 128, NB), 256>>>(out);
}

// round 3
// speedup vs baseline: 3.3266x; 3.3266x over previous
#include <cuda_runtime.h>
#include <cstdint>
#include <math.h>

#define NB 8
#define NC 256
#define NL 2048
#define BM 128
#define BN 128
#define BK 32
#define NTHREADS 256

// smem geometry (floats): row stride 36 (32 data + 4 pad) -> conflict-free frags
#define RS 36
#define TBUF (128 * RS)          // 4608 floats per operand tile
#define SMEM_FLOATS (4 * TBUF)   // 2 buffers x (A + B) = 73728 B

// ---------------- scratch ----------------
__device__ float g_xr[NB * NC * NL];
__device__ float g_Wr[3 * NL * NL];
__device__ float g_Qt[NB * NL * NC];   // [b][l][c]  (scaled + tf32-rounded)
__device__ float g_Kt[NB * NL * NC];   // [b][m][c]  (tf32-rounded)
__device__ float g_V [NB * NC * NL];   // [b][c][m]  (tf32-rounded)
__device__ float g_S [NB * NL * NL];   // scores -> probs (tf32-rounded)

// ---------------- helpers ----------------
__device__ __forceinline__ uint32_t smem_u32(const void* p) {
    uint32_t a;
    asm("{ .reg .u64 t; cvta.to.shared.u64 t, %1; cvt.u32.u64 %0, t; }"
        : "=r"(a) : "l"(p));
    return a;
}
__device__ __forceinline__ float rna_tf32(float x) {
    uint32_t u;
    asm("cvt.rna.tf32.f32 %0, %1;" : "=r"(u) : "f"(x));
    return __uint_as_float(u);
}
__device__ __forceinline__ void cp_async16(uint32_t dst, const void* src) {
    asm volatile("cp.async.cg.shared.global [%0], [%1], 16;" :: "r"(dst), "l"(src));
}
__device__ __forceinline__ void mma_tf32(float& d0, float& d1, float& d2, float& d3,
                                         float a0, float a1, float a2, float a3,
                                         float b0, float b1) {
    asm volatile(
        "mma.sync.aligned.m16n8k8.row.col.f32.tf32.tf32.f32 "
        "{%0,%1,%2,%3}, {%4,%5,%6,%7}, {%8,%9}, {%0,%1,%2,%3};"
        : "+f"(d0), "+f"(d1), "+f"(d2), "+f"(d3)
        : "r"(__float_as_uint(a0)), "r"(__float_as_uint(a1)),
          "r"(__float_as_uint(a2)), "r"(__float_as_uint(a3)),
          "r"(__float_as_uint(b0)), "r"(__float_as_uint(b1)));
}

// ---------------------------------------------------------------------------
// tf32 mma.sync GEMM:  C[M,N] = A[M,K] * B[N,K]^T  (both K-major fp32 storage
// holding tf32-rounded values; fp32 accumulate)
// MODE 0: plain store
// MODE 1: +bias, tf32-round, store                      (V projection)
// MODE 2: (+bias)*scale, tf32-round, transposed store   (Q/K projection)
// ---------------------------------------------------------------------------
template <int MODE>
__global__ __launch_bounds__(NTHREADS)
void gemm_mma(const float* __restrict__ A, const float* __restrict__ B,
              float* __restrict__ C, const float* __restrict__ bias,
              int K, int ldA, int ldB, int ldC,
              size_t Az, size_t Bz, size_t Cz, float scale)
{
    extern __shared__ float smem[];

    const int tid = threadIdx.x;
    const int wid = tid >> 5;
    const int lane = tid & 31;
    const int g = lane >> 2;      // group id (rows / B-cols)
    const int t = lane & 3;       // thread in group (k)
    const int wm = (wid & 1) * 64;
    const int wn = (wid >> 1) * 32;

    const int z = blockIdx.z;
    A += (size_t)z * Az;
    B += (size_t)z * Bz;
    const int r0 = blockIdx.y * BM;
    const int c0 = blockIdx.x * BN;

    const uint32_t sbase = smem_u32(smem);

    float acc[4][4][4];
#pragma unroll
    for (int i = 0; i < 4; i++)
#pragma unroll
        for (int j = 0; j < 4; j++)
#pragma unroll
            for (int k = 0; k < 4; k++) acc[i][j][k] = 0.0f;

    const int nchunks = K / BK;

    // cp.async loaders: 1024 float4 per operand per chunk; 256 thr x 4
    const int lrow = tid >> 3;          // 0..31 (x4 passes -> 128 rows)
    const int lc4  = (tid & 7) * 4;     // 0..28

    auto load_chunk = [&](int i) {
        const int s = i & 1;
        const uint32_t dA = sbase + (uint32_t)(s * TBUF) * 4u;
        const uint32_t dB = sbase + (uint32_t)((2 + s) * TBUF) * 4u;
        const float* Ab = A + (size_t)r0 * ldA + (size_t)i * BK;
        const float* Bb = B + (size_t)c0 * ldB + (size_t)i * BK;
#pragma unroll
        for (int p = 0; p < 4; p++) {
            const int row = lrow + p * 32;
            cp_async16(dA + (uint32_t)(row * RS + lc4) * 4u, Ab + (size_t)row * ldA + lc4);
            cp_async16(dB + (uint32_t)(row * RS + lc4) * 4u, Bb + (size_t)row * ldB + lc4);
        }
        asm volatile("cp.async.commit_group;");
    };

    load_chunk(0);

    for (int j = 0; j < nchunks; j++) {
        asm volatile("cp.async.wait_group 0;");
        __syncthreads();
        if (j + 1 < nchunks) load_chunk(j + 1);

        const int s = j & 1;
        const float* As = smem + s * TBUF;
        const float* Bs = smem + (2 + s) * TBUF;

#pragma unroll
        for (int k8 = 0; k8 < 4; k8++) {
            const int kb = k8 * 8;
            float a[4][4], b[4][2];
#pragma unroll
            for (int mt = 0; mt < 4; mt++) {
                const float* ap = As + (wm + mt * 16 + g) * RS + kb + t;
                a[mt][0] = ap[0];
                a[mt][1] = ap[8 * RS];
                a[mt][2] = ap[4];
                a[mt][3] = ap[8 * RS + 4];
            }
#pragma unroll
            for (int nt = 0; nt < 4; nt++) {
                const float* bp = Bs + (wn + nt * 8 + g) * RS + kb + t;
                b[nt][0] = bp[0];
                b[nt][1] = bp[4];
            }
#pragma unroll
            for (int mt = 0; mt < 4; mt++)
#pragma unroll
                for (int nt = 0; nt < 4; nt++)
                    mma_tf32(acc[mt][nt][0], acc[mt][nt][1], acc[mt][nt][2], acc[mt][nt][3],
                             a[mt][0], a[mt][1], a[mt][2], a[mt][3],
                             b[nt][0], b[nt][1]);
        }
        __syncthreads();
    }

    // ---------------- epilogue ----------------
    if (MODE == 0 || MODE == 1) {
        float* Cb = C + (size_t)z * Cz;
#pragma unroll
        for (int mt = 0; mt < 4; mt++) {
            const int row = r0 + wm + mt * 16 + g;
#pragma unroll
            for (int nt = 0; nt < 4; nt++) {
                const int col = c0 + wn + nt * 8 + 2 * t;
                float v0 = acc[mt][nt][0], v1 = acc[mt][nt][1];
                float v2 = acc[mt][nt][2], v3 = acc[mt][nt][3];
                if (MODE == 1) {
                    const float b0 = bias[col], b1 = bias[col + 1];
                    v0 = rna_tf32(v0 + b0); v1 = rna_tf32(v1 + b1);
                    v2 = rna_tf32(v2 + b0); v3 = rna_tf32(v3 + b1);
                }
                *(float2*)&Cb[(size_t)row * ldC + col]       = make_float2(v0, v1);
                *(float2*)&Cb[(size_t)(row + 8) * ldC + col] = make_float2(v2, v3);
            }
        }
    } else {
        // MODE 2: rows are (b*NC + c), cols are l; write C[b][l][c]
        const int bb = r0 >> 8;               // r0 / NC (BM=128 divides NC=256)
        const int cl0 = r0 & (NC - 1);
        float* Cb = C + (size_t)bb * NL * NC;
#pragma unroll
        for (int mt = 0; mt < 4; mt++) {
            const int cA = cl0 + wm + mt * 16 + g;
#pragma unroll
            for (int nt = 0; nt < 4; nt++) {
                const int l0 = c0 + wn + nt * 8 + 2 * t;
                const float b0 = bias[l0], b1 = bias[l0 + 1];
                Cb[(size_t)l0 * NC + cA]           = rna_tf32((acc[mt][nt][0] + b0) * scale);
                Cb[(size_t)(l0 + 1) * NC + cA]     = rna_tf32((acc[mt][nt][1] + b1) * scale);
                Cb[(size_t)l0 * NC + cA + 8]       = rna_tf32((acc[mt][nt][2] + b0) * scale);
                Cb[(size_t)(l0 + 1) * NC + cA + 8] = rna_tf32((acc[mt][nt][3] + b1) * scale);
            }
        }
    }
}

// ---------------------------------------------------------------------------
__global__ void round_kernel(const float* __restrict__ src, float* __restrict__ dst, int n4)
{
    const int i = blockIdx.x * blockDim.x + threadIdx.x;
    if (i < n4) {
        float4 v = ((const float4*)src)[i];
        v.x = rna_tf32(v.x); v.y = rna_tf32(v.y);
        v.z = rna_tf32(v.z); v.w = rna_tf32(v.w);
        ((float4*)dst)[i] = v;
    }
}

// ---------------------------------------------------------------------------
__global__ void softmax_kernel()
{
    const int row = blockIdx.x;
    float* p = g_S + (size_t)row * NL;
    const int tid = threadIdx.x;

    float4 v[2];
    float m = -1e30f;
#pragma unroll
    for (int j = 0; j < 2; j++) {
        v[j] = *(const float4*)&p[(tid + j * 256) * 4];
        m = fmaxf(m, fmaxf(fmaxf(v[j].x, v[j].y), fmaxf(v[j].z, v[j].w)));
    }

    __shared__ float red[256];
    red[tid] = m;
    __syncthreads();
    for (int s = 128; s > 0; s >>= 1) {
        if (tid < s) red[tid] = fmaxf(red[tid], red[tid + s]);
        __syncthreads();
    }
    m = red[0];
    __syncthreads();

    float sum = 0.0f;
#pragma unroll
    for (int j = 0; j < 2; j++) {
        v[j].x = __expf(v[j].x - m); sum += v[j].x;
        v[j].y = __expf(v[j].y - m); sum += v[j].y;
        v[j].z = __expf(v[j].z - m); sum += v[j].z;
        v[j].w = __expf(v[j].w - m); sum += v[j].w;
    }
    red[tid] = sum;
    __syncthreads();
    for (int s = 128; s > 0; s >>= 1) {
        if (tid < s) red[tid] += red[tid + s];
        __syncthreads();
    }
    const float inv = 1.0f / red[0];

#pragma unroll
    for (int j = 0; j < 2; j++) {
        float4 o;
        o.x = rna_tf32(v[j].x * inv); o.y = rna_tf32(v[j].y * inv);
        o.z = rna_tf32(v[j].z * inv); o.w = rna_tf32(v[j].w * inv);
        *(float4*)&p[(tid + j * 256) * 4] = o;
    }
}

// ---------------------------------------------------------------------------
extern "C" void kernel_launch(void* const* d_in, const int* in_sizes, int n_in,
                              void* d_out, int out_size)
{
    const float* x  = (const float*)d_in[0];
    const float* Wq = (const float*)d_in[1];
    const float* bq = (const float*)d_in[2];
    const float* Wk = (const float*)d_in[3];
    const float* bk = (const float*)d_in[4];
    const float* Wv = (const float*)d_in[5];
    const float* bv = (const float*)d_in[6];
    float* out = (float*)d_out;

    float *xr, *Wr, *Qt, *Kt, *V, *S;
    cudaGetSymbolAddress((void**)&xr, g_xr);
    cudaGetSymbolAddress((void**)&Wr, g_Wr);
    cudaGetSymbolAddress((void**)&Qt, g_Qt);
    cudaGetSymbolAddress((void**)&Kt, g_Kt);
    cudaGetSymbolAddress((void**)&V,  g_V);
    cudaGetSymbolAddress((void**)&S,  g_S);

    const int smem_bytes = SMEM_FLOATS * 4;  // 73728
    static bool attr_done = false;
    if (!attr_done) {
        cudaFuncSetAttribute((const void*)gemm_mma<0>, cudaFuncAttributeMaxDynamicSharedMemorySize, smem_bytes);
        cudaFuncSetAttribute((const void*)gemm_mma<1>, cudaFuncAttributeMaxDynamicSharedMemorySize, smem_bytes);
        cudaFuncSetAttribute((const void*)gemm_mma<2>, cudaFuncAttributeMaxDynamicSharedMemorySize, smem_bytes);
        attr_done = true;
    }

    // 1) round inputs to tf32 (unbiased rna)
    {
        const int n4x = NB * NC * NL / 4;
        round_kernel<<<(n4x + 255) / 256, 256>>>(x, xr, n4x);
        const int n4w = NL * NL / 4;
        round_kernel<<<(n4w + 255) / 256, 256>>>(Wq, Wr + 0 * (size_t)NL * NL, n4w);
        round_kernel<<<(n4w + 255) / 256, 256>>>(Wk, Wr + 1 * (size_t)NL * NL, n4w);
        round_kernel<<<(n4w + 255) / 256, 256>>>(Wv, Wr + 2 * (size_t)NL * NL, n4w);
    }

    const float qscale = 0.022097086912079612f;  // 1/sqrt(2048)

    // 2) projections (A = xr [2048 x 2048], B = W [2048 x 2048], K-major)
    gemm_mma<2><<<dim3(NL / BN, (NB * NC) / BM, 1), NTHREADS, smem_bytes>>>(
        xr, Wr + 0 * (size_t)NL * NL, Qt, bq, NL, NL, NL, NC, 0, 0, 0, qscale);
    gemm_mma<2><<<dim3(NL / BN, (NB * NC) / BM, 1), NTHREADS, smem_bytes>>>(
        xr, Wr + 1 * (size_t)NL * NL, Kt, bk, NL, NL, NL, NC, 0, 0, 0, 1.0f);
    gemm_mma<1><<<dim3(NL / BN, (NB * NC) / BM, 1), NTHREADS, smem_bytes>>>(
        xr, Wr + 2 * (size_t)NL * NL, V, bv, NL, NL, NL, NL, 0, 0, 0, 1.0f);

    // 3) scores: S[b][l][m] = Qt[b][l][:] . Kt[b][m][:]   (K = 256)
    gemm_mma<0><<<dim3(NL / BN, NL / BM, NB), NTHREADS, smem_bytes>>>(
        Qt, Kt, S, nullptr, NC, NC, NC, NL,
        (size_t)NL * NC, (size_t)NL * NC, (size_t)NL * NL, 1.0f);

    // 4) softmax (+ tf32 round of P)
    softmax_kernel<<<NB * NL, 256>>>();

    // 5) out[b][c][l] = V[b][c][:] . P[b][l][:]   (K = 2048)
    gemm_mma<0><<<dim3(NL / BN, NC / BM, NB), NTHREADS, smem_bytes>>>(
        V, S, out, nullptr, NL, NL, NL, NL,
        (size_t)NC * NL, (size_t)NL * NL, (size_t)NC * NL, 1.0f);
}

// round 4
// speedup vs baseline: 3.3950x; 1.0206x over previous
#include <cuda_runtime.h>
#include <cstdint>
#include <math.h>

#define NB 8
#define NC 256
#define NL 2048
#define BM 128
#define BN 128
#define BK 32
#define NTHREADS 256
#define NSTAGE 3

// smem geometry (floats): row stride 36 (32 data + 4 pad) -> conflict-free frags
#define RS 36
#define TBUF (128 * RS)                    // 4608 floats per operand tile
#define SMEM_FLOATS (NSTAGE * 2 * TBUF)    // 27648 floats = 110592 B

// ---------------- scratch ----------------
__device__ float g_Qt[NB * NL * NC];   // [b][l][c]  (scaled + tf32-rounded)
__device__ float g_Kt[NB * NL * NC];   // [b][m][c]  (tf32-rounded)
__device__ float g_V [NB * NC * NL];   // [b][c][m]  (tf32-rounded)
__device__ float g_S [NB * NL * NL];   // scores -> probs (tf32-rounded)

// ---------------- helpers ----------------
__device__ __forceinline__ uint32_t smem_u32(const void* p) {
    uint32_t a;
    asm("{ .reg .u64 t; cvta.to.shared.u64 t, %1; cvt.u32.u64 %0, t; }"
        : "=r"(a) : "l"(p));
    return a;
}
__device__ __forceinline__ float rna_tf32(float x) {
    uint32_t u;
    asm("cvt.rna.tf32.f32 %0, %1;" : "=r"(u) : "f"(x));
    return __uint_as_float(u);
}
__device__ __forceinline__ void cp_async16(uint32_t dst, const void* src) {
    asm volatile("cp.async.cg.shared.global [%0], [%1], 16;" :: "r"(dst), "l"(src));
}
__device__ __forceinline__ void mma_tf32(float& d0, float& d1, float& d2, float& d3,
                                         float a0, float a1, float a2, float a3,
                                         float b0, float b1) {
    asm volatile(
        "mma.sync.aligned.m16n8k8.row.col.f32.tf32.tf32.f32 "
        "{%0,%1,%2,%3}, {%4,%5,%6,%7}, {%8,%9}, {%0,%1,%2,%3};"
        : "+f"(d0), "+f"(d1), "+f"(d2), "+f"(d3)
        : "r"(__float_as_uint(a0)), "r"(__float_as_uint(a1)),
          "r"(__float_as_uint(a2)), "r"(__float_as_uint(a3)),
          "r"(__float_as_uint(b0)), "r"(__float_as_uint(b1)));
}

// Shared mainloop body. ROUND_FRAG: apply rna_tf32 to fragments (raw fp32 inputs).
// acc[4][4][4] laid out [mtile][ntile][reg].
template <int ROUND_FRAG>
__device__ __forceinline__ void gemm_mainloop(
    const float* __restrict__ A, const float* __restrict__ B,
    int K, int ldA, int ldB, int r0, int c0,
    float* smem, int tid, int wm, int wn, int g, int t,
    float acc[4][4][4])
{
    const uint32_t sbase = smem_u32(smem);
    const int nchunks = K / BK;

    const int lrow = tid >> 3;          // 0..31 (x4 passes -> 128 rows)
    const int lc4  = (tid & 7) * 4;     // 0..28

    auto load_chunk = [&](int i) {
        const int s = i % NSTAGE;
        const uint32_t dA = sbase + (uint32_t)(s * 2 * TBUF) * 4u;
        const uint32_t dB = dA + (uint32_t)TBUF * 4u;
        const float* Ab = A + (size_t)r0 * ldA + (size_t)i * BK;
        const float* Bb = B + (size_t)c0 * ldB + (size_t)i * BK;
#pragma unroll
        for (int p = 0; p < 4; p++) {
            const int row = lrow + p * 32;
            cp_async16(dA + (uint32_t)(row * RS + lc4) * 4u, Ab + (size_t)row * ldA + lc4);
            cp_async16(dB + (uint32_t)(row * RS + lc4) * 4u, Bb + (size_t)row * ldB + lc4);
        }
    };

    // prologue: 2 chunks in flight
    load_chunk(0);
    asm volatile("cp.async.commit_group;");
    if (nchunks > 1) load_chunk(1);
    asm volatile("cp.async.commit_group;");

    for (int j = 0; j < nchunks; j++) {
        asm volatile("cp.async.wait_group 1;");   // chunk j resident
        __syncthreads();                          // + compute j-1 fully drained
        if (j + 2 < nchunks) load_chunk(j + 2);
        asm volatile("cp.async.commit_group;");

        const int s = j % NSTAGE;
        const float* As = smem + s * 2 * TBUF;
        const float* Bs = As + TBUF;

#pragma unroll
        for (int k8 = 0; k8 < 4; k8++) {
            const int kb = k8 * 8;
            float a[4][4], b[4][2];
#pragma unroll
            for (int mt = 0; mt < 4; mt++) {
                const float* ap = As + (wm + mt * 16 + g) * RS + kb + t;
                a[mt][0] = ap[0];
                a[mt][1] = ap[8 * RS];
                a[mt][2] = ap[4];
                a[mt][3] = ap[8 * RS + 4];
                if (ROUND_FRAG) {
                    a[mt][0] = rna_tf32(a[mt][0]); a[mt][1] = rna_tf32(a[mt][1]);
                    a[mt][2] = rna_tf32(a[mt][2]); a[mt][3] = rna_tf32(a[mt][3]);
                }
            }
#pragma unroll
            for (int nt = 0; nt < 4; nt++) {
                const float* bp = Bs + (wn + nt * 8 + g) * RS + kb + t;
                b[nt][0] = bp[0];
                b[nt][1] = bp[4];
                if (ROUND_FRAG) {
                    b[nt][0] = rna_tf32(b[nt][0]); b[nt][1] = rna_tf32(b[nt][1]);
                }
            }
#pragma unroll
            for (int mt = 0; mt < 4; mt++)
#pragma unroll
                for (int nt = 0; nt < 4; nt++)
                    mma_tf32(acc[mt][nt][0], acc[mt][nt][1], acc[mt][nt][2], acc[mt][nt][3],
                             a[mt][0], a[mt][1], a[mt][2], a[mt][3],
                             b[nt][0], b[nt][1]);
        }
    }
}

// ---------------------------------------------------------------------------
// Merged QKV projection GEMM.  A = x (raw), B = Wq|Wk|Wv selected per tile.
// Global cols 0..2047 -> Q (transposed store, *1/sqrt(L)), 2048..4095 -> K
// (transposed store), 4096..6143 -> V (plain store). All epilogues: +bias,
// tf32-round. Fragments tf32-rounded in registers (no prepass).
// ---------------------------------------------------------------------------
__global__ __launch_bounds__(NTHREADS, 2)
void qkv_gemm(const float* __restrict__ x,
              const float* __restrict__ Wq, const float* __restrict__ bq,
              const float* __restrict__ Wk, const float* __restrict__ bk,
              const float* __restrict__ Wv, const float* __restrict__ bv)
{
    extern __shared__ float smem[];

    const int tid = threadIdx.x;
    const int wid = tid >> 5;
    const int lane = tid & 31;
    const int g = lane >> 2;
    const int t = lane & 3;
    const int wm = (wid & 1) * 64;
    const int wn = (wid >> 1) * 32;

    const int r0 = blockIdx.y * BM;
    const int gc0 = blockIdx.x * BN;          // global col 0..6143
    const int widx = gc0 >> 11;               // 0=Q 1=K 2=V
    const int c0 = gc0 & (NL - 1);            // col within weight

    const float* W    = (widx == 0) ? Wq : (widx == 1) ? Wk : Wv;
    const float* bias = (widx == 0) ? bq : (widx == 1) ? bk : bv;
    const float scale = (widx == 0) ? 0.022097086912079612f : 1.0f;

    float acc[4][4][4];
#pragma unroll
    for (int i = 0; i < 4; i++)
#pragma unroll
        for (int j = 0; j < 4; j++)
#pragma unroll
            for (int k = 0; k < 4; k++) acc[i][j][k] = 0.0f;

    gemm_mainloop<1>(x, W, NL, NL, NL, r0, c0, smem, tid, wm, wn, g, t, acc);

    const int bb  = r0 >> 8;          // batch (BM=128 divides NC=256)
    const int cl0 = r0 & (NC - 1);    // channel within batch

    if (widx < 2) {
        // transposed store: T[b][l][c] = rna((acc + bias[l]) * scale)
        float* Tb = ((widx == 0) ? g_Qt : g_Kt) + (size_t)bb * NL * NC;
#pragma unroll
        for (int mt = 0; mt < 4; mt++) {
            const int cA = cl0 + wm + mt * 16 + g;
#pragma unroll
            for (int nt = 0; nt < 4; nt++) {
                const int l0 = c0 + wn + nt * 8 + 2 * t;
                const float b0 = bias[l0], b1 = bias[l0 + 1];
                Tb[(size_t)l0 * NC + cA]           = rna_tf32((acc[mt][nt][0] + b0) * scale);
                Tb[(size_t)(l0 + 1) * NC + cA]     = rna_tf32((acc[mt][nt][1] + b1) * scale);
                Tb[(size_t)l0 * NC + cA + 8]       = rna_tf32((acc[mt][nt][2] + b0) * scale);
                Tb[(size_t)(l0 + 1) * NC + cA + 8] = rna_tf32((acc[mt][nt][3] + b1) * scale);
            }
        }
    } else {
        // V: plain row-major store V[r][m]
#pragma unroll
        for (int mt = 0; mt < 4; mt++) {
            const int row = r0 + wm + mt * 16 + g;
#pragma unroll
            for (int nt = 0; nt < 4; nt++) {
                const int col = c0 + wn + nt * 8 + 2 * t;
                const float b0 = bias[col], b1 = bias[col + 1];
                float v0 = rna_tf32(acc[mt][nt][0] + b0);
                float v1 = rna_tf32(acc[mt][nt][1] + b1);
                float v2 = rna_tf32(acc[mt][nt][2] + b0);
                float v3 = rna_tf32(acc[mt][nt][3] + b1);
                *(float2*)&g_V[(size_t)row * NL + col]       = make_float2(v0, v1);
                *(float2*)&g_V[(size_t)(row + 8) * NL + col] = make_float2(v2, v3);
            }
        }
    }
}

// ---------------------------------------------------------------------------
// Generic GEMM (inputs pre-rounded): C[M,N] = A[M,K] * B[N,K]^T, plain store.
// ---------------------------------------------------------------------------
__global__ __launch_bounds__(NTHREADS, 2)
void gemm0(const float* __restrict__ A, const float* __restrict__ B,
           float* __restrict__ C, int K, int ldA, int ldB, int ldC,
           size_t Az, size_t Bz, size_t Cz)
{
    extern __shared__ float smem[];

    const int tid = threadIdx.x;
    const int wid = tid >> 5;
    const int lane = tid & 31;
    const int g = lane >> 2;
    const int t = lane & 3;
    const int wm = (wid & 1) * 64;
    const int wn = (wid >> 1) * 32;

    const int z = blockIdx.z;
    A += (size_t)z * Az;
    B += (size_t)z * Bz;
    const int r0 = blockIdx.y * BM;
    const int c0 = blockIdx.x * BN;

    float acc[4][4][4];
#pragma unroll
    for (int i = 0; i < 4; i++)
#pragma unroll
        for (int j = 0; j < 4; j++)
#pragma unroll
            for (int k = 0; k < 4; k++) acc[i][j][k] = 0.0f;

    gemm_mainloop<0>(A, B, K, ldA, ldB, r0, c0, smem, tid, wm, wn, g, t, acc);

    float* Cb = C + (size_t)z * Cz;
#pragma unroll
    for (int mt = 0; mt < 4; mt++) {
        const int row = r0 + wm + mt * 16 + g;
#pragma unroll
        for (int nt = 0; nt < 4; nt++) {
            const int col = c0 + wn + nt * 8 + 2 * t;
            *(float2*)&Cb[(size_t)row * ldC + col] =
                make_float2(acc[mt][nt][0], acc[mt][nt][1]);
            *(float2*)&Cb[(size_t)(row + 8) * ldC + col] =
                make_float2(acc[mt][nt][2], acc[mt][nt][3]);
        }
    }
}

// ---------------------------------------------------------------------------
__global__ void softmax_kernel()
{
    const int row = blockIdx.x;
    float* p = g_S + (size_t)row * NL;
    const int tid = threadIdx.x;

    float4 v[2];
    float m = -1e30f;
#pragma unroll
    for (int j = 0; j < 2; j++) {
        v[j] = *(const float4*)&p[(tid + j * 256) * 4];
        m = fmaxf(m, fmaxf(fmaxf(v[j].x, v[j].y), fmaxf(v[j].z, v[j].w)));
    }

    __shared__ float red[256];
    red[tid] = m;
    __syncthreads();
    for (int s = 128; s > 0; s >>= 1) {
        if (tid < s) red[tid] = fmaxf(red[tid], red[tid + s]);
        __syncthreads();
    }
    m = red[0];
    __syncthreads();

    float sum = 0.0f;
#pragma unroll
    for (int j = 0; j < 2; j++) {
        v[j].x = __expf(v[j].x - m); sum += v[j].x;
        v[j].y = __expf(v[j].y - m); sum += v[j].y;
        v[j].z = __expf(v[j].z - m); sum += v[j].z;
        v[j].w = __expf(v[j].w - m); sum += v[j].w;
    }
    red[tid] = sum;
    __syncthreads();
    for (int s = 128; s > 0; s >>= 1) {
        if (tid < s) red[tid] += red[tid + s];
        __syncthreads();
    }
    const float inv = 1.0f / red[0];

#pragma unroll
    for (int j = 0; j < 2; j++) {
        float4 o;
        o.x = rna_tf32(v[j].x * inv); o.y = rna_tf32(v[j].y * inv);
        o.z = rna_tf32(v[j].z * inv); o.w = rna_tf32(v[j].w * inv);
        *(float4*)&p[(tid + j * 256) * 4] = o;
    }
}

// ---------------------------------------------------------------------------
extern "C" void kernel_launch(void* const* d_in, const int* in_sizes, int n_in,
                              void* d_out, int out_size)
{
    const float* x  = (const float*)d_in[0];
    const float* Wq = (const float*)d_in[1];
    const float* bq = (const float*)d_in[2];
    const float* Wk = (const float*)d_in[3];
    const float* bk = (const float*)d_in[4];
    const float* Wv = (const float*)d_in[5];
    const float* bv = (const float*)d_in[6];
    float* out = (float*)d_out;

    float *Qt, *Kt, *V, *S;
    cudaGetSymbolAddress((void**)&Qt, g_Qt);
    cudaGetSymbolAddress((void**)&Kt, g_Kt);
    cudaGetSymbolAddress((void**)&V,  g_V);
    cudaGetSymbolAddress((void**)&S,  g_S);

    const int smem_bytes = SMEM_FLOATS * 4;  // 110592
    cudaFuncSetAttribute((const void*)qkv_gemm, cudaFuncAttributeMaxDynamicSharedMemorySize, smem_bytes);
    cudaFuncSetAttribute((const void*)gemm0,    cudaFuncAttributeMaxDynamicSharedMemorySize, smem_bytes);

    // 1) fused QKV projections (rounding folded into fragments)
    qkv_gemm<<<dim3(3 * NL / BN, (NB * NC) / BM, 1), NTHREADS, smem_bytes>>>(
        x, Wq, bq, Wk, bk, Wv, bv);

    // 2) scores: S[b][l][m] = Qt[b][l][:] . Kt[b][m][:]   (K = 256)
    gemm0<<<dim3(NL / BN, NL / BM, NB), NTHREADS, smem_bytes>>>(
        Qt, Kt, S, NC, NC, NC, NL,
        (size_t)NL * NC, (size_t)NL * NC, (size_t)NL * NL);

    // 3) softmax (+ tf32 round of P)
    softmax_kernel<<<NB * NL, 256>>>();

    // 4) out[b][c][l] = V[b][c][:] . P[b][l][:]   (K = 2048)
    gemm0<<<dim3(NL / BN, NC / BM, NB), NTHREADS, smem_bytes>>>(
        V, S, out, NL, NL, NL, NL,
        (size_t)NC * NL, (size_t)NL * NL, (size_t)NC * NL);
}

// round 5
// speedup vs baseline: 3.5907x; 1.0577x over previous
#include <cuda_runtime.h>
#include <cstdint>
#include <math.h>

#define NB 8
#define NC 256
#define NL 2048
#define BM 128
#define BN 128
#define BK 32
#define NTHREADS 256
#define NSTAGE 3

// smem geometry (floats): row stride 36 (32 data + 4 pad)
// rows start at bank 4r mod 32 -> ldmatrix 8-row phases conflict-free,
// and (row*36 + {0,4,8,...})*4B is 16B-aligned (144 = 9*16).
#define RS 36
#define TBUF (128 * RS)                    // 4608 floats per operand tile
#define SMEM_FLOATS (NSTAGE * 2 * TBUF)    // 27648 floats = 110592 B

// ---------------- scratch ----------------
__device__ float g_Qt[NB * NL * NC];   // [b][l][c]  (scaled + tf32-rounded)
__device__ float g_Kt[NB * NL * NC];   // [b][m][c]  (tf32-rounded)
__device__ float g_V [NB * NC * NL];   // [b][c][m]  (tf32-rounded)
__device__ float g_S [NB * NL * NL];   // scores -> probs (tf32-rounded)

// ---------------- helpers ----------------
__device__ __forceinline__ uint32_t smem_u32(const void* p) {
    uint32_t a;
    asm("{ .reg .u64 t; cvta.to.shared.u64 t, %1; cvt.u32.u64 %0, t; }"
        : "=r"(a) : "l"(p));
    return a;
}
__device__ __forceinline__ float rna_tf32(float x) {
    uint32_t u;
    asm("cvt.rna.tf32.f32 %0, %1;" : "=r"(u) : "f"(x));
    return __uint_as_float(u);
}
__device__ __forceinline__ uint32_t rna_tf32_u(uint32_t x) {
    uint32_t u;
    asm("cvt.rna.tf32.f32 %0, %1;" : "=r"(u) : "f"(__uint_as_float(x)));
    return u;
}
__device__ __forceinline__ void cp_async16(uint32_t dst, const void* src) {
    asm volatile("cp.async.cg.shared.global [%0], [%1], 16;" :: "r"(dst), "l"(src));
}
__device__ __forceinline__ void ldsm4(uint32_t& r0, uint32_t& r1, uint32_t& r2,
                                      uint32_t& r3, uint32_t addr) {
    asm volatile("ldmatrix.sync.aligned.m8n8.x4.shared.b16 {%0,%1,%2,%3}, [%4];"
                 : "=r"(r0), "=r"(r1), "=r"(r2), "=r"(r3) : "r"(addr));
}
__device__ __forceinline__ void mma_tf32(float& d0, float& d1, float& d2, float& d3,
                                         uint32_t a0, uint32_t a1, uint32_t a2, uint32_t a3,
                                         uint32_t b0, uint32_t b1) {
    asm volatile(
        "mma.sync.aligned.m16n8k8.row.col.f32.tf32.tf32.f32 "
        "{%0,%1,%2,%3}, {%4,%5,%6,%7}, {%8,%9}, {%0,%1,%2,%3};"
        : "+f"(d0), "+f"(d1), "+f"(d2), "+f"(d3)
        : "r"(a0), "r"(a1), "r"(a2), "r"(a3), "r"(b0), "r"(b1));
}

// Shared mainloop. ROUND_FRAG: rna_tf32 on fragments (raw fp32 inputs).
template <int ROUND_FRAG>
__device__ __forceinline__ void gemm_mainloop(
    const float* __restrict__ A, const float* __restrict__ B,
    int K, int ldA, int ldB, int r0, int c0,
    float* smem, int tid, int wm, int wn, int lane,
    float acc[4][4][4])
{
    const uint32_t sbase = smem_u32(smem);
    const int nchunks = K / BK;

    const int lrow = tid >> 3;          // 0..31 (x4 passes -> 128 rows)
    const int lc4  = (tid & 7) * 4;     // 0..28

    // ldmatrix per-thread row/col selectors
    const int aRow = wm + (lane & 15);               // A rows g / g+8 per mt
    const int aCol = (lane >> 4) * 4;                // k half (0 / +4)
    const int bRow = wn + ((lane >> 4) & 1) * 8 + (lane & 7);  // nt pair rows
    const int bCol = ((lane >> 3) & 1) * 4;

    auto load_chunk = [&](int i) {
        const int s = i % NSTAGE;
        const uint32_t dA = sbase + (uint32_t)(s * 2 * TBUF) * 4u;
        const uint32_t dB = dA + (uint32_t)TBUF * 4u;
        const float* Ab = A + (size_t)r0 * ldA + (size_t)i * BK;
        const float* Bb = B + (size_t)c0 * ldB + (size_t)i * BK;
#pragma unroll
        for (int p = 0; p < 4; p++) {
            const int row = lrow + p * 32;
            cp_async16(dA + (uint32_t)(row * RS + lc4) * 4u, Ab + (size_t)row * ldA + lc4);
            cp_async16(dB + (uint32_t)(row * RS + lc4) * 4u, Bb + (size_t)row * ldB + lc4);
        }
    };

    load_chunk(0);
    asm volatile("cp.async.commit_group;");
    if (nchunks > 1) load_chunk(1);
    asm volatile("cp.async.commit_group;");

    for (int j = 0; j < nchunks; j++) {
        asm volatile("cp.async.wait_group 1;");
        __syncthreads();
        if (j + 2 < nchunks) load_chunk(j + 2);
        asm volatile("cp.async.commit_group;");

        const int s = j % NSTAGE;
        const uint32_t sA = sbase + (uint32_t)(s * 2 * TBUF) * 4u;
        const uint32_t sB = sA + (uint32_t)TBUF * 4u;
        const uint32_t aBase = sA + (uint32_t)(aRow * RS + aCol) * 4u;
        const uint32_t bBase = sB + (uint32_t)(bRow * RS + bCol) * 4u;

#pragma unroll
        for (int k8 = 0; k8 < 4; k8++) {
            const int kb = k8 * 8;
            uint32_t a[4][4], b[2][4];
#pragma unroll
            for (int mt = 0; mt < 4; mt++)
                ldsm4(a[mt][0], a[mt][1], a[mt][2], a[mt][3],
                      aBase + (uint32_t)((mt * 16) * RS + kb) * 4u);
#pragma unroll
            for (int ntp = 0; ntp < 2; ntp++)
                ldsm4(b[ntp][0], b[ntp][1], b[ntp][2], b[ntp][3],
                      bBase + (uint32_t)((ntp * 16) * RS + kb) * 4u);
            if (ROUND_FRAG) {
#pragma unroll
                for (int mt = 0; mt < 4; mt++)
#pragma unroll
                    for (int r = 0; r < 4; r++) a[mt][r] = rna_tf32_u(a[mt][r]);
#pragma unroll
                for (int ntp = 0; ntp < 2; ntp++)
#pragma unroll
                    for (int r = 0; r < 4; r++) b[ntp][r] = rna_tf32_u(b[ntp][r]);
            }
#pragma unroll
            for (int mt = 0; mt < 4; mt++)
#pragma unroll
                for (int nt = 0; nt < 4; nt++)
                    mma_tf32(acc[mt][nt][0], acc[mt][nt][1], acc[mt][nt][2], acc[mt][nt][3],
                             a[mt][0], a[mt][1], a[mt][2], a[mt][3],
                             b[nt >> 1][(nt & 1) * 2], b[nt >> 1][(nt & 1) * 2 + 1]);
        }
    }
}

// ---------------------------------------------------------------------------
// Merged QKV projection GEMM (cols 0..2047 -> Q transposed+scaled,
// 2048..4095 -> K transposed, 4096..6143 -> V plain). Frag-side tf32 rounding.
// ---------------------------------------------------------------------------
__global__ __launch_bounds__(NTHREADS, 2)
void qkv_gemm(const float* __restrict__ x,
              const float* __restrict__ Wq, const float* __restrict__ bq,
              const float* __restrict__ Wk, const float* __restrict__ bk,
              const float* __restrict__ Wv, const float* __restrict__ bv)
{
    extern __shared__ float smem[];

    const int tid = threadIdx.x;
    const int wid = tid >> 5;
    const int lane = tid & 31;
    const int g = lane >> 2;
    const int t = lane & 3;
    const int wm = (wid & 1) * 64;
    const int wn = (wid >> 1) * 32;

    const int r0 = blockIdx.y * BM;
    const int gc0 = blockIdx.x * BN;
    const int widx = gc0 >> 11;
    const int c0 = gc0 & (NL - 1);

    const float* W    = (widx == 0) ? Wq : (widx == 1) ? Wk : Wv;
    const float* bias = (widx == 0) ? bq : (widx == 1) ? bk : bv;
    const float scale = (widx == 0) ? 0.022097086912079612f : 1.0f;

    float acc[4][4][4];
#pragma unroll
    for (int i = 0; i < 4; i++)
#pragma unroll
        for (int j = 0; j < 4; j++)
#pragma unroll
            for (int k = 0; k < 4; k++) acc[i][j][k] = 0.0f;

    gemm_mainloop<1>(x, W, NL, NL, NL, r0, c0, smem, tid, wm, wn, lane, acc);

    const int bb  = r0 >> 8;
    const int cl0 = r0 & (NC - 1);

    if (widx < 2) {
        float* Tb = ((widx == 0) ? g_Qt : g_Kt) + (size_t)bb * NL * NC;
#pragma unroll
        for (int mt = 0; mt < 4; mt++) {
            const int cA = cl0 + wm + mt * 16 + g;
#pragma unroll
            for (int nt = 0; nt < 4; nt++) {
                const int l0 = c0 + wn + nt * 8 + 2 * t;
                const float b0 = bias[l0], b1 = bias[l0 + 1];
                Tb[(size_t)l0 * NC + cA]           = rna_tf32((acc[mt][nt][0] + b0) * scale);
                Tb[(size_t)(l0 + 1) * NC + cA]     = rna_tf32((acc[mt][nt][1] + b1) * scale);
                Tb[(size_t)l0 * NC + cA + 8]       = rna_tf32((acc[mt][nt][2] + b0) * scale);
                Tb[(size_t)(l0 + 1) * NC + cA + 8] = rna_tf32((acc[mt][nt][3] + b1) * scale);
            }
        }
    } else {
#pragma unroll
        for (int mt = 0; mt < 4; mt++) {
            const int row = r0 + wm + mt * 16 + g;
#pragma unroll
            for (int nt = 0; nt < 4; nt++) {
                const int col = c0 + wn + nt * 8 + 2 * t;
                const float b0 = bias[col], b1 = bias[col + 1];
                float v0 = rna_tf32(acc[mt][nt][0] + b0);
                float v1 = rna_tf32(acc[mt][nt][1] + b1);
                float v2 = rna_tf32(acc[mt][nt][2] + b0);
                float v3 = rna_tf32(acc[mt][nt][3] + b1);
                *(float2*)&g_V[(size_t)row * NL + col]       = make_float2(v0, v1);
                *(float2*)&g_V[(size_t)(row + 8) * NL + col] = make_float2(v2, v3);
            }
        }
    }
}

// ---------------------------------------------------------------------------
// Generic GEMM (inputs pre-rounded): C[M,N] = A[M,K] * B[N,K]^T, plain store.
// ---------------------------------------------------------------------------
__global__ __launch_bounds__(NTHREADS, 2)
void gemm0(const float* __restrict__ A, const float* __restrict__ B,
           float* __restrict__ C, int K, int ldA, int ldB, int ldC,
           size_t Az, size_t Bz, size_t Cz)
{
    extern __shared__ float smem[];

    const int tid = threadIdx.x;
    const int wid = tid >> 5;
    const int lane = tid & 31;
    const int g = lane >> 2;
    const int t = lane & 3;
    const int wm = (wid & 1) * 64;
    const int wn = (wid >> 1) * 32;

    const int z = blockIdx.z;
    A += (size_t)z * Az;
    B += (size_t)z * Bz;
    const int r0 = blockIdx.y * BM;
    const int c0 = blockIdx.x * BN;

    float acc[4][4][4];
#pragma unroll
    for (int i = 0; i < 4; i++)
#pragma unroll
        for (int j = 0; j < 4; j++)
#pragma unroll
            for (int k = 0; k < 4; k++) acc[i][j][k] = 0.0f;

    gemm_mainloop<0>(A, B, K, ldA, ldB, r0, c0, smem, tid, wm, wn, lane, acc);

    float* Cb = C + (size_t)z * Cz;
#pragma unroll
    for (int mt = 0; mt < 4; mt++) {
        const int row = r0 + wm + mt * 16 + g;
#pragma unroll
        for (int nt = 0; nt < 4; nt++) {
            const int col = c0 + wn + nt * 8 + 2 * t;
            *(float2*)&Cb[(size_t)row * ldC + col] =
                make_float2(acc[mt][nt][0], acc[mt][nt][1]);
            *(float2*)&Cb[(size_t)(row + 8) * ldC + col] =
                make_float2(acc[mt][nt][2], acc[mt][nt][3]);
        }
    }
}

// ---------------------------------------------------------------------------
__global__ void softmax_kernel()
{
    const int row = blockIdx.x;
    float* p = g_S + (size_t)row * NL;
    const int tid = threadIdx.x;

    float4 v[2];
    float m = -1e30f;
#pragma unroll
    for (int j = 0; j < 2; j++) {
        v[j] = *(const float4*)&p[(tid + j * 256) * 4];
        m = fmaxf(m, fmaxf(fmaxf(v[j].x, v[j].y), fmaxf(v[j].z, v[j].w)));
    }

    __shared__ float red[256];
    red[tid] = m;
    __syncthreads();
    for (int s = 128; s > 0; s >>= 1) {
        if (tid < s) red[tid] = fmaxf(red[tid], red[tid + s]);
        __syncthreads();
    }
    m = red[0];
    __syncthreads();

    float sum = 0.0f;
#pragma unroll
    for (int j = 0; j < 2; j++) {
        v[j].x = __expf(v[j].x - m); sum += v[j].x;
        v[j].y = __expf(v[j].y - m); sum += v[j].y;
        v[j].z = __expf(v[j].z - m); sum += v[j].z;
        v[j].w = __expf(v[j].w - m); sum += v[j].w;
    }
    red[tid] = sum;
    __syncthreads();
    for (int s = 128; s > 0; s >>= 1) {
        if (tid < s) red[tid] += red[tid + s];
        __syncthreads();
    }
    const float inv = 1.0f / red[0];

#pragma unroll
    for (int j = 0; j < 2; j++) {
        float4 o;
        o.x = rna_tf32(v[j].x * inv); o.y = rna_tf32(v[j].y * inv);
        o.z = rna_tf32(v[j].z * inv); o.w = rna_tf32(v[j].w * inv);
        *(float4*)&p[(tid + j * 256) * 4] = o;
    }
}

// ---------------------------------------------------------------------------
extern "C" void kernel_launch(void* const* d_in, const int* in_sizes, int n_in,
                              void* d_out, int out_size)
{
    const float* x  = (const float*)d_in[0];
    const float* Wq = (const float*)d_in[1];
    const float* bq = (const float*)d_in[2];
    const float* Wk = (const float*)d_in[3];
    const float* bk = (const float*)d_in[4];
    const float* Wv = (const float*)d_in[5];
    const float* bv = (const float*)d_in[6];
    float* out = (float*)d_out;

    float *Qt, *Kt, *V, *S;
    cudaGetSymbolAddress((void**)&Qt, g_Qt);
    cudaGetSymbolAddress((void**)&Kt, g_Kt);
    cudaGetSymbolAddress((void**)&V,  g_V);
    cudaGetSymbolAddress((void**)&S,  g_S);

    const int smem_bytes = SMEM_FLOATS * 4;  // 110592
    cudaFuncSetAttribute((const void*)qkv_gemm, cudaFuncAttributeMaxDynamicSharedMemorySize, smem_bytes);
    cudaFuncSetAttribute((const void*)gemm0,    cudaFuncAttributeMaxDynamicSharedMemorySize, smem_bytes);

    // 1) fused QKV projections
    qkv_gemm<<<dim3(3 * NL / BN, (NB * NC) / BM, 1), NTHREADS, smem_bytes>>>(
        x, Wq, bq, Wk, bk, Wv, bv);

    // 2) scores: S[b][l][m] = Qt[b][l][:] . Kt[b][m][:]   (K = 256)
    gemm0<<<dim3(NL / BN, NL / BM, NB), NTHREADS, smem_bytes>>>(
        Qt, Kt, S, NC, NC, NC, NL,
        (size_t)NL * NC, (size_t)NL * NC, (size_t)NL * NL);

    // 3) softmax (+ tf32 round of P)
    softmax_kernel<<<NB * NL, 256>>>();

    // 4) out[b][c][l] = V[b][c][:] . P[b][l][:]   (K = 2048)
    gemm0<<<dim3(NL / BN, NC / BM, NB), NTHREADS, smem_bytes>>>(
        V, S, out, NL, NL, NL, NL,
        (size_t)NC * NL, (size_t)NL * NL, (size_t)NC * NL);
}